// round 13
// baseline (speedup 1.0000x reference)
#include <cuda_runtime.h>
#include <cuda_bf16.h>
#include <cstdint>
#include <math.h>

#define BATCH 512
#define NSEQ  101
#define R_TOT (BATCH*NSEQ)   // 51712
#define EDIM  128
#define NHEAD 8
#define DK    16
#define FF    512
#define NBLK_BN 808          // = R_TOT/64

typedef unsigned long long ull;

// ---------------- scratch (device globals; allocation-free) ----------------
__device__ float g_x[R_TOT*EDIM];
__device__ float g_qkv[3*R_TOT*EDIM];
__device__ float g_y[R_TOT*EDIM];
__device__ float g_p1[NBLK_BN*EDIM];
__device__ float g_p2[NBLK_BN*EDIM];
__device__ float g_s1[EDIM];
__device__ float g_t1[EDIM];
__device__ float g_s2[EDIM];
__device__ float g_t2[EDIM];
__device__ float g_bqkv[3*3*EDIM];
__device__ uint32_t g_wh[3*98304];
__device__ uint32_t g_wl[3*98304];
// activation images (swizzled bf16 hi/lo, region = 64 rows x 32 k = 1024 u32)
__device__ uint32_t g_xih[R_TOT*64];
__device__ uint32_t g_xil[R_TOT*64];
__device__ uint32_t g_tih[R_TOT*64];
__device__ uint32_t g_til[R_TOT*64];
__device__ uint32_t g_yih[R_TOT*64];
__device__ uint32_t g_yil[R_TOT*64];
__device__ uint32_t g_hih[R_TOT*256];
__device__ uint32_t g_hil[R_TOT*256];

// ======================= helpers =======================
__device__ __forceinline__ uint32_t smem_u32(const void* p) {
    uint32_t a;
    asm("{ .reg .u64 t; cvta.to.shared.u64 t, %1; cvt.u32.u64 %0, t; }" : "=r"(a) : "l"(p));
    return a;
}
__device__ __forceinline__ void ldsm_x4(uint32_t* r, uint32_t addr) {
    asm volatile("ldmatrix.sync.aligned.m8n8.x4.shared.b16 {%0,%1,%2,%3}, [%4];"
        : "=r"(r[0]), "=r"(r[1]), "=r"(r[2]), "=r"(r[3]) : "r"(addr));
}
__device__ __forceinline__ void mma16816(float* c, const uint32_t* a, const uint32_t* b) {
    asm volatile(
        "mma.sync.aligned.m16n8k16.row.col.f32.bf16.bf16.f32 "
        "{%0,%1,%2,%3}, {%4,%5,%6,%7}, {%8,%9}, {%0,%1,%2,%3};"
        : "+f"(c[0]), "+f"(c[1]), "+f"(c[2]), "+f"(c[3])
        : "r"(a[0]), "r"(a[1]), "r"(a[2]), "r"(a[3]), "r"(b[0]), "r"(b[1]));
}
__device__ __forceinline__ uint32_t pack_bf2(float x, float y) {
    __nv_bfloat162 t;
    t.x = __float2bfloat16(x); t.y = __float2bfloat16(y);
    return *reinterpret_cast<uint32_t*>(&t);
}
__device__ __forceinline__ void split_pair(float x, float y, uint32_t& hi, uint32_t& lo) {
    __nv_bfloat16 h0 = __float2bfloat16(x);
    __nv_bfloat16 h1 = __float2bfloat16(y);
    __nv_bfloat162 hp; hp.x = h0; hp.y = h1;
    hi = *(uint32_t*)&hp;
    lo = pack_bf2(x - __bfloat162float(h0), y - __bfloat162float(h1));
}
__device__ __forceinline__ void cp_async16(uint32_t saddr, const void* g) {
    asm volatile("cp.async.cg.shared.global [%0], [%1], 16;" :: "r"(saddr), "l"(g));
}
__device__ __forceinline__ void cp_commit() { asm volatile("cp.async.commit_group;"); }
__device__ __forceinline__ void cp_wait0() { asm volatile("cp.async.wait_group 0;"); }

__device__ __forceinline__ uint32_t sw_off(int row, int col8) {
    return (uint32_t)((row << 6) + ((col8 ^ ((row >> 1) & 3)) << 4));
}
__device__ __forceinline__ uint32_t img_u32(int rl, int kl) {
    return (sw_off(rl, kl >> 3) + ((kl & 7) << 1)) >> 2;
}

// ================== weight pre-conversion ==================
__global__ __launch_bounds__(256)
void w_convert(const float* __restrict__ Wq, const float* __restrict__ Wk,
               const float* __restrict__ Wv, const float* __restrict__ Wo,
               const float* __restrict__ Wf1, const float* __restrict__ Wf2,
               const float* __restrict__ bq, const float* __restrict__ bk,
               const float* __restrict__ bv, float* __restrict__ bqkv,
               uint32_t* __restrict__ oh, uint32_t* __restrict__ ol) {
    int mode = blockIdx.y;
    int idx = blockIdx.x * 256 + threadIdx.x;
    if (mode == 0 && idx < 3*3*EDIM) {
        int layer = idx / 384, w = (idx / 128) % 3, c = idx & 127;
        const float* src = (w == 0) ? bq : (w == 1) ? bk : bv;
        bqkv[idx] = src[layer * EDIM + c];
    }
    const float* src;
    int N, K, npairs, dstoff;
    if (mode < 12) {
        int layer = mode >> 2, w = mode & 3;
        const float* s;
        if (w == 0) s = Wq; else if (w == 1) s = Wk; else if (w == 2) s = Wv; else s = Wo;
        src = s + layer * 16384;
        N = 128; K = 128; npairs = 8192; dstoff = layer * 98304 + w * 8192;
    } else if (mode < 15) {
        int layer = mode - 12;
        src = Wf1 + layer * 65536;
        N = 512; K = 128; npairs = 32768; dstoff = layer * 98304 + 32768;
    } else {
        int layer = mode - 15;
        src = Wf2 + layer * 65536;
        N = 128; K = 512; npairs = 32768; dstoff = layer * 98304 + 65536;
    }
    if (idx >= npairs) return;
    int n = idx & (N - 1);
    int k2g = idx / N;
    float x0 = src[(long)(2 * k2g) * N + n];
    float x1 = src[(long)(2 * k2g + 1) * N + n];
    int c = k2g >> 4, kl = (k2g & 15) * 2;
    int nb = n >> 7, nl = n & 127;
    uint32_t u = (uint32_t)dstoff + (uint32_t)(nb * (K >> 5) + c) * 2048
               + ((sw_off(nl, kl >> 3) + ((kl & 7) << 1)) >> 2);
    uint32_t hi, lo;
    split_pair(x0, x1, hi, lo);
    oh[u] = hi; ol[u] = lo;
}

// ================== activation -> normed bf16 hi/lo image ==================
__global__ __launch_bounds__(256)
void conv_norm(const float* __restrict__ X,
               const float* __restrict__ S, const float* __restrict__ T,
               uint32_t* __restrict__ oh, uint32_t* __restrict__ ol) {
    int idx = blockIdx.x * 256 + threadIdx.x;
    int row = idx >> 6, p2 = idx & 63;
    float2 a = *(const float2*)(X + (long)row * 128 + 2 * p2);
    if (S) {
        int c0 = 2 * p2;
        a.x = a.x * __ldg(S + c0)     + __ldg(T + c0);
        a.y = a.y * __ldg(S + c0 + 1) + __ldg(T + c0 + 1);
    }
    int rl = row & 63, c = p2 >> 4, kl = (2 * p2) & 31;
    uint32_t u = ((uint32_t)(row >> 6) * 4 + c) * 1024 + img_u32(rl, kl);
    uint32_t hi, lo;
    split_pair(a.x, a.y, hi, lo);
    oh[u] = hi; ol[u] = lo;
}

// ================== K=128 preload GEMM: whole operands resident, one barrier ==================
// smem: AH 16KB @0, AL @16384, BH 32KB @32768, BL @65536; total 98304 B, 2 CTAs/SM
#define PA_H 0
#define PA_L 16384
#define PB_H 32768
#define PB_L 65536
#define PRE_SMEM 98304
template<int RELU, int STATS, int WIMG>
__global__ __launch_bounds__(256, 2)
void gemm_pre(const uint32_t* __restrict__ Ah, const uint32_t* __restrict__ Al,
              const uint32_t* __restrict__ Wh_, const uint32_t* __restrict__ Wl_, int wstride,
              const float* __restrict__ bias_, int bstride,
              const float* __restrict__ res,
              const float* __restrict__ Rs_, const float* __restrict__ Rt_,
              float* __restrict__ C_, long cstride,
              uint32_t* __restrict__ Hh, uint32_t* __restrict__ Hl,
              float* __restrict__ P1, float* __restrict__ P2,
              int Nout)
{
    extern __shared__ __align__(128) char sm[];
    const uint32_t usm = smem_u32(sm);

    const uint32_t* Wh = Wh_ + (long)blockIdx.z * wstride;
    const uint32_t* Wl = Wl_ + (long)blockIdx.z * wstride;
    const float* bias = bias_ + blockIdx.z * bstride;
    float* C = C_ + (long)blockIdx.z * cstride;

    const int tid  = threadIdx.x;
    const int lane = tid & 31;
    const int warp = tid >> 5;
    const int wm = (warp & 1) * 32;
    const int wn = (warp >> 1) * 32;
    const int m0 = blockIdx.y * 64;
    const int n0 = blockIdx.x * 128;

    // ---- prologue: one cp.async burst for everything ----
    {
        const uint32_t* ah_src = Ah + (long)blockIdx.y * 4096;
        const uint32_t* al_src = Al + (long)blockIdx.y * 4096;
        const uint32_t* bh_src = Wh + (long)blockIdx.x * 8192;
        const uint32_t* bl_src = Wl + (long)blockIdx.x * 8192;
#pragma unroll
        for (int i = 0; i < 4; i++) {
            int o = tid * 4 + i * 1024;
            cp_async16(usm + PA_H + o * 4, ah_src + o);
            cp_async16(usm + PA_L + o * 4, al_src + o);
        }
#pragma unroll
        for (int i = 0; i < 8; i++) {
            int o = tid * 4 + i * 1024;
            cp_async16(usm + PB_H + o * 4, bh_src + o);
            cp_async16(usm + PB_L + o * 4, bl_src + o);
        }
        cp_commit();
        cp_wait0();
        __syncthreads();
    }

    float acc[2][4][4];
#pragma unroll
    for (int i = 0; i < 2; i++)
#pragma unroll
        for (int j = 0; j < 4; j++)
#pragma unroll
            for (int q = 0; q < 4; q++) acc[i][j][q] = 0.f;

    // ---- mainloop: 8 kk-steps, no barriers ----
#pragma unroll
    for (int kk = 0; kk < 128; kk += 16) {
        const uint32_t cb_a = (uint32_t)((kk >> 5) << 12);
        const uint32_t cb_b = (uint32_t)((kk >> 5) << 13);
        const int kl = kk & 31;
        uint32_t ah[2][4], al[2][4];
#pragma unroll
        for (int mi = 0; mi < 2; mi++) {
            int arow = wm + mi * 16 + (lane & 15);
            uint32_t off = usm + PA_H + cb_a + sw_off(arow, (kl >> 3) + (lane >> 4));
            ldsm_x4(ah[mi], off);
            ldsm_x4(al[mi], off + (PA_L - PA_H));
        }
#pragma unroll
        for (int np = 0; np < 2; np++) {
            uint32_t bh[4], bl[4];
            int nrow = wn + np * 16 + (lane & 7) + ((lane >> 4) << 3);
            uint32_t boff = usm + PB_H + cb_b + sw_off(nrow, (kl >> 3) + ((lane >> 3) & 1));
            ldsm_x4(bh, boff);
            ldsm_x4(bl, boff + (PB_L - PB_H));
#pragma unroll
            for (int t = 0; t < 2; t++) {
#pragma unroll
                for (int mi = 0; mi < 2; mi++) {
                    float* cc = acc[mi][np * 2 + t];
                    mma16816(cc, ah[mi], bh + t * 2);
                    mma16816(cc, ah[mi], bl + t * 2);
                    mma16816(cc, al[mi], bh + t * 2);
                }
            }
        }
    }

    const int group = lane >> 2, tig = lane & 3;

    if (WIMG) {
        __syncthreads();
        uint32_t* smH = (uint32_t*)sm;
        uint32_t* smL = smH + 4096;
#pragma unroll
        for (int mi = 0; mi < 2; mi++) {
#pragma unroll
            for (int np = 0; np < 2; np++) {
#pragma unroll
                for (int t = 0; t < 2; t++) {
                    float* cc = acc[mi][np * 2 + t];
                    int rl = wm + mi * 16 + group;
                    int cl = wn + np * 16 + t * 8 + tig * 2;
                    float b0 = bias[n0 + cl], b1 = bias[n0 + cl + 1];
                    float v0 = cc[0] + b0, v1 = cc[1] + b1;
                    float v2 = cc[2] + b0, v3 = cc[3] + b1;
                    if (RELU) {
                        v0 = fmaxf(v0, 0.f); v1 = fmaxf(v1, 0.f);
                        v2 = fmaxf(v2, 0.f); v3 = fmaxf(v3, 0.f);
                    }
                    int ch = cl >> 5, kl = cl & 31;
                    uint32_t o1 = ch * 1024 + img_u32(rl, kl);
                    uint32_t o2 = ch * 1024 + img_u32(rl + 8, kl);
                    uint32_t hi, lo;
                    split_pair(v0, v1, hi, lo);
                    smH[o1] = hi; smL[o1] = lo;
                    split_pair(v2, v3, hi, lo);
                    smH[o2] = hi; smL[o2] = lo;
                }
            }
        }
        __syncthreads();
        long gbase = ((long)blockIdx.y * (Nout >> 5) + (n0 >> 5)) * 1024;
        uint4* gh = (uint4*)(Hh + gbase);
        uint4* gl = (uint4*)(Hl + gbase);
        const uint4* sh4 = (const uint4*)smH;
        const uint4* sl4 = (const uint4*)smL;
#pragma unroll
        for (int i = 0; i < 4; i++) {
            gh[tid + i * 256] = sh4[tid + i * 256];
            gl[tid + i * 256] = sl4[tid + i * 256];
        }
        return;
    }

    float s1L[8], s2L[8];
    if (STATS) {
#pragma unroll
        for (int i = 0; i < 8; i++) { s1L[i] = 0.f; s2L[i] = 0.f; }
    }
#pragma unroll
    for (int mi = 0; mi < 2; mi++) {
#pragma unroll
        for (int np = 0; np < 2; np++) {
#pragma unroll
            for (int t = 0; t < 2; t++) {
                float* cc = acc[mi][np * 2 + t];
                int row = m0 + wm + mi * 16 + group;
                int col = n0 + wn + np * 16 + t * 8 + tig * 2;
                float b0 = bias[col], b1 = bias[col + 1];
                float v0 = cc[0] + b0, v1 = cc[1] + b1;
                float v2 = cc[2] + b0, v3 = cc[3] + b1;
                if (res) {
                    float r0 = res[(long)row * 128 + col];
                    float r1 = res[(long)row * 128 + col + 1];
                    float r2 = res[(long)(row + 8) * 128 + col];
                    float r3 = res[(long)(row + 8) * 128 + col + 1];
                    if (Rs_) {
                        float s0 = __ldg(Rs_ + col), s1 = __ldg(Rs_ + col + 1);
                        float t0 = __ldg(Rt_ + col), t1 = __ldg(Rt_ + col + 1);
                        r0 = r0 * s0 + t0; r1 = r1 * s1 + t1;
                        r2 = r2 * s0 + t0; r3 = r3 * s1 + t1;
                    }
                    v0 += r0; v1 += r1; v2 += r2; v3 += r3;
                }
                if (RELU) {
                    v0 = fmaxf(v0, 0.f); v1 = fmaxf(v1, 0.f);
                    v2 = fmaxf(v2, 0.f); v3 = fmaxf(v3, 0.f);
                }
                if (STATS) {
                    int kk = np * 4 + t * 2;
                    s1L[kk]     += v0 + v2;
                    s1L[kk + 1] += v1 + v3;
                    s2L[kk]     += v0 * v0 + v2 * v2;
                    s2L[kk + 1] += v1 * v1 + v3 * v3;
                }
                float2 p0 = {v0, v1}, p1 = {v2, v3};
                *(float2*)(C + (long)row * Nout + col) = p0;
                *(float2*)(C + (long)(row + 8) * Nout + col) = p1;
            }
        }
    }
    if (STATS) {
#pragma unroll
        for (int m = 4; m <= 16; m <<= 1) {
#pragma unroll
            for (int kk = 0; kk < 8; kk++) {
                s1L[kk] += __shfl_xor_sync(0xFFFFFFFF, s1L[kk], m);
                s2L[kk] += __shfl_xor_sync(0xFFFFFFFF, s2L[kk], m);
            }
        }
        __syncthreads();
        float* sb = (float*)sm;
        if (lane < 4) {
#pragma unroll
            for (int kk = 0; kk < 8; kk++) {
                int col = wn + ((kk >> 2) * 16) + (((kk >> 1) & 1) * 8) + lane * 2 + (kk & 1);
                int idx2 = ((warp & 1) << 7) + col;
                sb[idx2] = s1L[kk];
                sb[256 + idx2] = s2L[kk];
            }
        }
        __syncthreads();
        if (tid < 128) {
            P1[blockIdx.y * 128 + tid] = sb[tid] + sb[128 + tid];
            P2[blockIdx.y * 128 + tid] = sb[256 + tid] + sb[384 + tid];
        }
    }
}

// ================== chunked GEMM (K=512: FF2) ==================
#define OFF_A(buf,hl) (((((buf)<<1)+(hl))<<12))
#define OFF_B(buf,hl) (16384 + (((((buf)<<1)+(hl))<<13)))
template<int RELU, int STATS>
__global__ __launch_bounds__(256, 3)
void gemm_tc(const uint32_t* __restrict__ Ah, const uint32_t* __restrict__ Al,
             const uint32_t* __restrict__ Wh, const uint32_t* __restrict__ Wl,
             const float* __restrict__ bias,
             const float* __restrict__ res,
             const float* __restrict__ Rs_, const float* __restrict__ Rt_,
             float* __restrict__ C,
             float* __restrict__ P1, float* __restrict__ P2,
             int K, int Nout)
{
    __shared__ __align__(128) char sm[49152];
    const uint32_t usm = smem_u32(sm);

    const int tid  = threadIdx.x;
    const int lane = tid & 31;
    const int warp = tid >> 5;
    const int wm = (warp & 1) * 32;
    const int wn = (warp >> 1) * 32;
    const int m0 = blockIdx.y * 64;
    const int n0 = blockIdx.x * 128;
    const int nchunks = K >> 5;
    const long bregbase = (long)blockIdx.x * nchunks;
    const long aregbase = (long)blockIdx.y * nchunks;

    float acc[2][4][4];
#pragma unroll
    for (int i = 0; i < 2; i++)
#pragma unroll
        for (int j = 0; j < 4; j++)
#pragma unroll
            for (int q = 0; q < 4; q++) acc[i][j][q] = 0.f;

    {
        const uint32_t* bh = Wh + bregbase * 2048 + tid * 8;
        const uint32_t* bl = Wl + bregbase * 2048 + tid * 8;
        cp_async16(usm + OFF_B(0,0) + tid * 32,      bh);
        cp_async16(usm + OFF_B(0,0) + tid * 32 + 16, bh + 4);
        cp_async16(usm + OFF_B(0,1) + tid * 32,      bl);
        cp_async16(usm + OFF_B(0,1) + tid * 32 + 16, bl + 4);
        cp_async16(usm + OFF_A(0,0) + tid * 16, Ah + aregbase * 1024 + tid * 4);
        cp_async16(usm + OFF_A(0,1) + tid * 16, Al + aregbase * 1024 + tid * 4);
        cp_commit();
        cp_wait0();
        __syncthreads();
    }

    for (int c = 0; c < nchunks; c++) {
        const int cur = c & 1, nxt = cur ^ 1;
        const bool hn = (c + 1) < nchunks;
        if (hn) {
            const uint32_t* bh = Wh + (bregbase + c + 1) * 2048 + tid * 8;
            const uint32_t* bl = Wl + (bregbase + c + 1) * 2048 + tid * 8;
            cp_async16(usm + OFF_B(nxt,0) + tid * 32,      bh);
            cp_async16(usm + OFF_B(nxt,0) + tid * 32 + 16, bh + 4);
            cp_async16(usm + OFF_B(nxt,1) + tid * 32,      bl);
            cp_async16(usm + OFF_B(nxt,1) + tid * 32 + 16, bl + 4);
            cp_async16(usm + OFF_A(nxt,0) + tid * 16, Ah + (aregbase + c + 1) * 1024 + tid * 4);
            cp_async16(usm + OFF_A(nxt,1) + tid * 16, Al + (aregbase + c + 1) * 1024 + tid * 4);
            cp_commit();
        }
#pragma unroll
        for (int kk = 0; kk < 32; kk += 16) {
            uint32_t ah[2][4], al[2][4];
#pragma unroll
            for (int mi = 0; mi < 2; mi++) {
                int arow = wm + mi * 16 + (lane & 15);
                uint32_t off = OFF_A(cur,0) + sw_off(arow, (kk >> 3) + (lane >> 4));
                ldsm_x4(ah[mi], usm + off);
                ldsm_x4(al[mi], usm + off + 4096);
            }
#pragma unroll
            for (int np = 0; np < 2; np++) {
                uint32_t bh[4], bl[4];
                int nrow = wn + np * 16 + (lane & 7) + ((lane >> 4) << 3);
                uint32_t boff = OFF_B(cur,0) + sw_off(nrow, (kk >> 3) + ((lane >> 3) & 1));
                ldsm_x4(bh, usm + boff);
                ldsm_x4(bl, usm + boff + 8192);
#pragma unroll
                for (int t = 0; t < 2; t++) {
#pragma unroll
                    for (int mi = 0; mi < 2; mi++) {
                        float* cc = acc[mi][np * 2 + t];
                        mma16816(cc, ah[mi], bh + t * 2);
                        mma16816(cc, ah[mi], bl + t * 2);
                        mma16816(cc, al[mi], bh + t * 2);
                    }
                }
            }
        }
        if (hn) {
            cp_wait0();
            __syncthreads();
        }
    }

    const int group = lane >> 2, tig = lane & 3;
    float s1L[8], s2L[8];
    if (STATS) {
#pragma unroll
        for (int i = 0; i < 8; i++) { s1L[i] = 0.f; s2L[i] = 0.f; }
    }
#pragma unroll
    for (int mi = 0; mi < 2; mi++) {
#pragma unroll
        for (int np = 0; np < 2; np++) {
#pragma unroll
            for (int t = 0; t < 2; t++) {
                float* cc = acc[mi][np * 2 + t];
                int row = m0 + wm + mi * 16 + group;
                int col = n0 + wn + np * 16 + t * 8 + tig * 2;
                float b0 = bias[col], b1 = bias[col + 1];
                float v0 = cc[0] + b0, v1 = cc[1] + b1;
                float v2 = cc[2] + b0, v3 = cc[3] + b1;
                if (res) {
                    float r0 = res[(long)row * 128 + col];
                    float r1 = res[(long)row * 128 + col + 1];
                    float r2 = res[(long)(row + 8) * 128 + col];
                    float r3 = res[(long)(row + 8) * 128 + col + 1];
                    if (Rs_) {
                        float s0 = __ldg(Rs_ + col), s1 = __ldg(Rs_ + col + 1);
                        float t0 = __ldg(Rt_ + col), t1 = __ldg(Rt_ + col + 1);
                        r0 = r0 * s0 + t0; r1 = r1 * s1 + t1;
                        r2 = r2 * s0 + t0; r3 = r3 * s1 + t1;
                    }
                    v0 += r0; v1 += r1; v2 += r2; v3 += r3;
                }
                if (RELU) {
                    v0 = fmaxf(v0, 0.f); v1 = fmaxf(v1, 0.f);
                    v2 = fmaxf(v2, 0.f); v3 = fmaxf(v3, 0.f);
                }
                if (STATS) {
                    int kk = np * 4 + t * 2;
                    s1L[kk]     += v0 + v2;
                    s1L[kk + 1] += v1 + v3;
                    s2L[kk]     += v0 * v0 + v2 * v2;
                    s2L[kk + 1] += v1 * v1 + v3 * v3;
                }
                float2 p0 = {v0, v1}, p1 = {v2, v3};
                *(float2*)(C + (long)row * Nout + col) = p0;
                *(float2*)(C + (long)(row + 8) * Nout + col) = p1;
            }
        }
    }
    if (STATS) {
#pragma unroll
        for (int m = 4; m <= 16; m <<= 1) {
#pragma unroll
            for (int kk = 0; kk < 8; kk++) {
                s1L[kk] += __shfl_xor_sync(0xFFFFFFFF, s1L[kk], m);
                s2L[kk] += __shfl_xor_sync(0xFFFFFFFF, s2L[kk], m);
            }
        }
        __syncthreads();
        float* sb = (float*)sm;
        if (lane < 4) {
#pragma unroll
            for (int kk = 0; kk < 8; kk++) {
                int col = wn + ((kk >> 2) * 16) + (((kk >> 1) & 1) * 8) + lane * 2 + (kk & 1);
                int idx2 = ((warp & 1) << 7) + col;
                sb[idx2] = s1L[kk];
                sb[256 + idx2] = s2L[kk];
            }
        }
        __syncthreads();
        if (tid < 128) {
            P1[blockIdx.y * 128 + tid] = sb[tid] + sb[128 + tid];
            P2[blockIdx.y * 128 + tid] = sb[256 + tid] + sb[384 + tid];
        }
    }
}

// ---------------- embedding ----------------
__global__ void embed_kernel(const float* __restrict__ s, const int* __restrict__ d,
                             const float* __restrict__ e_w, const float* __restrict__ e_b,
                             const float* __restrict__ ep_w, const float* __restrict__ ep_b,
                             float* __restrict__ x) {
    int r = blockIdx.x;
    int e = threadIdx.x;
    int n = r % NSEQ;
    float s0 = s[r*2+0], s1 = s[r*2+1];
    float out;
    if (n == 0) {
        out = ep_b[e] + s0*ep_w[e] + s1*ep_w[EDIM+e];
    } else {
        float dd = (float)d[r];
        out = e_b[e] + s0*e_w[e] + s1*e_w[EDIM+e] + dd*e_w[2*EDIM+e];
    }
    x[r*EDIM+e] = out;
}

// ---------------- attention: tensor-core (HMMA) flash-style, per (b,h) block ----------------
#define QK_STR 48
#define VT_STR 240
#define AQH 0
#define AQL 5376
#define AKH 10752
#define AKL 16128
#define AVH 21504
#define AVL 25344
#define ATTN_SM 29184
__global__ __launch_bounds__(224, 2)
void attn_kernel(const float* __restrict__ q, const float* __restrict__ k,
                 const float* __restrict__ v,
                 uint32_t* __restrict__ th, uint32_t* __restrict__ tl) {
    __shared__ __align__(128) char sm[ATTN_SM];
    const uint32_t usm = smem_u32(sm);
    int bh = blockIdx.x;
    int b = bh >> 3, h = bh & 7;
    int tid = threadIdx.x, lane = tid & 31, warp = tid >> 5;
    long base = (long)b * NSEQ * EDIM + h * DK;

    for (int i = tid; i < ATTN_SM/16; i += 224)
        ((uint4*)sm)[i] = make_uint4(0,0,0,0);
    __syncthreads();

    for (int idx = tid; idx < NSEQ*8; idx += 224) {
        int r = idx >> 3, d2 = idx & 7;
        float2 qv = *(const float2*)(q + base + (long)r*EDIM + 2*d2);
        float2 kv = *(const float2*)(k + base + (long)r*EDIM + 2*d2);
        float2 vv = *(const float2*)(v + base + (long)r*EDIM + 2*d2);
        uint32_t hi, lo;
        split_pair(qv.x, qv.y, hi, lo);
        *(uint32_t*)(sm + AQH + r*QK_STR + 4*d2) = hi;
        *(uint32_t*)(sm + AQL + r*QK_STR + 4*d2) = lo;
        split_pair(kv.x, kv.y, hi, lo);
        *(uint32_t*)(sm + AKH + r*QK_STR + 4*d2) = hi;
        *(uint32_t*)(sm + AKL + r*QK_STR + 4*d2) = lo;
        __nv_bfloat16 h0 = __float2bfloat16(vv.x);
        __nv_bfloat16 h1 = __float2bfloat16(vv.y);
        *(__nv_bfloat16*)(sm + AVH + (2*d2)*VT_STR + 2*r) = h0;
        *(__nv_bfloat16*)(sm + AVH + (2*d2+1)*VT_STR + 2*r) = h1;
        *(__nv_bfloat16*)(sm + AVL + (2*d2)*VT_STR + 2*r) =
            __float2bfloat16(vv.x - __bfloat162float(h0));
        *(__nv_bfloat16*)(sm + AVL + (2*d2+1)*VT_STR + 2*r) =
            __float2bfloat16(vv.y - __bfloat162float(h1));
    }
    __syncthreads();

    const int mt = warp;
    const int g = lane >> 2, tig = lane & 3;

    uint32_t qh[4], ql[4];
    {
        uint32_t addr = usm + AQH + (mt*16 + (lane & 15)) * QK_STR + ((lane >> 4) << 4);
        ldsm_x4(qh, addr);
        ldsm_x4(ql, addr + (AQL - AQH));
    }

    float sc[14][4];
#pragma unroll
    for (int i = 0; i < 14; i++)
#pragma unroll
        for (int j = 0; j < 4; j++) sc[i][j] = 0.f;
#pragma unroll
    for (int kp = 0; kp < 7; kp++) {
        uint32_t kbh[4], kbl[4];
        uint32_t addr = usm + AKH + (kp*16 + (lane & 7) + ((lane >> 4) << 3)) * QK_STR
                      + (((lane >> 3) & 1) << 4);
        ldsm_x4(kbh, addr);
        ldsm_x4(kbl, addr + (AKL - AKH));
#pragma unroll
        for (int t = 0; t < 2; t++) {
            float* cc = sc[2*kp + t];
            mma16816(cc, qh, kbh + t*2);
            mma16816(cc, qh, kbl + t*2);
            mma16816(cc, ql, kbh + t*2);
        }
    }

    float l0 = 0.f, l1 = 0.f;
#pragma unroll
    for (int nt = 0; nt < 14; nt++) {
        int colb = nt*8 + tig*2;
        float e0 = (colb     < NSEQ) ? __expf(sc[nt][0] * 0.25f) : 0.f;
        float e1 = (colb + 1 < NSEQ) ? __expf(sc[nt][1] * 0.25f) : 0.f;
        float e2 = (colb     < NSEQ) ? __expf(sc[nt][2] * 0.25f) : 0.f;
        float e3 = (colb + 1 < NSEQ) ? __expf(sc[nt][3] * 0.25f) : 0.f;
        sc[nt][0] = e0; sc[nt][1] = e1; sc[nt][2] = e2; sc[nt][3] = e3;
        l0 += e0 + e1; l1 += e2 + e3;
    }
    l0 += __shfl_xor_sync(0xFFFFFFFF, l0, 1);
    l0 += __shfl_xor_sync(0xFFFFFFFF, l0, 2);
    l1 += __shfl_xor_sync(0xFFFFFFFF, l1, 1);
    l1 += __shfl_xor_sync(0xFFFFFFFF, l1, 2);
    float inv0 = 1.f / l0, inv1 = 1.f / l1;

    float oa[2][4];
#pragma unroll
    for (int i = 0; i < 2; i++)
#pragma unroll
        for (int j = 0; j < 4; j++) oa[i][j] = 0.f;
#pragma unroll
    for (int kc = 0; kc < 7; kc++) {
        uint32_t ah4[4], al4[4];
        float* s0 = sc[2*kc]; float* s1 = sc[2*kc + 1];
        split_pair(s0[0], s0[1], ah4[0], al4[0]);
        split_pair(s0[2], s0[3], ah4[1], al4[1]);
        split_pair(s1[0], s1[1], ah4[2], al4[2]);
        split_pair(s1[2], s1[3], ah4[3], al4[3]);
        uint32_t vbh[4], vbl[4];
        uint32_t addr = usm + AVH + ((lane & 7) + ((lane >> 4) << 3)) * VT_STR
                      + (kc << 5) + (((lane >> 3) & 1) << 4);
        ldsm_x4(vbh, addr);
        ldsm_x4(vbl, addr + (AVL - AVH));
#pragma unroll
        for (int d = 0; d < 2; d++) {
            float* cc = oa[d];
            mma16816(cc, ah4, vbh + d*2);
            mma16816(cc, ah4, vbl + d*2);
            mma16816(cc, al4, vbh + d*2);
        }
    }

#pragma unroll
    for (int d = 0; d < 2; d++) {
        int qr = mt*16 + g;
        if (qr < NSEQ) {
            int row = b * NSEQ + qr;
            uint32_t regb = ((uint32_t)(row >> 6) * 4 + (h >> 1)) * 1024;
            int kl = (h & 1) * 16 + d*8 + 2*tig;
            uint32_t u = regb + img_u32(row & 63, kl);
            uint32_t hi, lo;
            split_pair(oa[d][0]*inv0, oa[d][1]*inv0, hi, lo);
            th[u] = hi; tl[u] = lo;
        }
        if (qr + 8 < NSEQ) {
            int row = b * NSEQ + qr + 8;
            uint32_t regb = ((uint32_t)(row >> 6) * 4 + (h >> 1)) * 1024;
            int kl = (h & 1) * 16 + d*8 + 2*tig;
            uint32_t u = regb + img_u32(row & 63, kl);
            uint32_t hi, lo;
            split_pair(oa[d][2]*inv1, oa[d][3]*inv1, hi, lo);
            th[u] = hi; tl[u] = lo;
        }
    }
}

// ---------------- batchnorm finalize (one block per channel) ----------------
__global__ __launch_bounds__(256)
void bn_final_kernel(const float* __restrict__ p1, const float* __restrict__ p2,
                     const float* __restrict__ g, const float* __restrict__ be,
                     float* __restrict__ s, float* __restrict__ t) {
    int c = blockIdx.x;
    int tid = threadIdx.x, lane = tid & 31, warp = tid >> 5;
    float s1 = 0.f, s2 = 0.f;
    for (int b = tid; b < NBLK_BN; b += 256) {
        s1 += p1[(long)b*EDIM + c];
        s2 += p2[(long)b*EDIM + c];
    }
#pragma unroll
    for (int m = 16; m >= 1; m >>= 1) {
        s1 += __shfl_xor_sync(0xFFFFFFFF, s1, m);
        s2 += __shfl_xor_sync(0xFFFFFFFF, s2, m);
    }
    __shared__ float sh[2][8];
    if (lane == 0) { sh[0][warp] = s1; sh[1][warp] = s2; }
    __syncthreads();
    if (tid == 0) {
        float a1 = 0.f, a2 = 0.f;
#pragma unroll
        for (int w = 0; w < 8; w++) { a1 += sh[0][w]; a2 += sh[1][w]; }
        float mu = a1 / (float)R_TOT;
        float var = a2 / (float)R_TOT - mu*mu;
        float istd = rsqrtf(var + 1e-5f);
        float scv = istd * g[c];
        s[c] = scv;
        t[c] = be[c] - mu * scv;
    }
}

__global__ __launch_bounds__(256)
void bn_norm_kernel(const float* __restrict__ y,
                    const float* __restrict__ s, const float* __restrict__ t,
                    float* __restrict__ outp) {
    long idx = (long)blockIdx.x * blockDim.x + threadIdx.x;
    if (idx < (long)R_TOT*EDIM) {
        int c = (int)(idx & 127);
        outp[idx] = y[idx] * s[c] + t[c];
    }
}

// ---------------- orchestration ----------------
extern "C" void kernel_launch(void* const* d_in, const int* in_sizes, int n_in,
                              void* d_out, int out_size) {
    const float* s    = (const float*)d_in[0];
    const int*   dd   = (const int*)  d_in[1];
    const float* e_w  = (const float*)d_in[2];
    const float* e_b  = (const float*)d_in[3];
    const float* ep_w = (const float*)d_in[4];
    const float* ep_b = (const float*)d_in[5];
    const float* Wq   = (const float*)d_in[6];
    const float* bq   = (const float*)d_in[7];
    const float* Wk   = (const float*)d_in[8];
    const float* bk   = (const float*)d_in[9];
    const float* Wv   = (const float*)d_in[10];
    const float* bv   = (const float*)d_in[11];
    const float* Wo   = (const float*)d_in[12];
    const float* bo   = (const float*)d_in[13];
    const float* Wf1  = (const float*)d_in[14];
    const float* bf1  = (const float*)d_in[15];
    const float* Wf2  = (const float*)d_in[16];
    const float* bf2  = (const float*)d_in[17];
    const float* g1   = (const float*)d_in[18];
    const float* be1  = (const float*)d_in[19];
    const float* g2   = (const float*)d_in[20];
    const float* be2  = (const float*)d_in[21];
    float* out = (float*)d_out;

    float *x, *qkv, *y, *p1, *p2, *s1b, *t1b, *s2b, *t2b, *bqkv;
    uint32_t *wh, *wl, *xih, *xil, *tih, *til, *yih, *yil, *hih, *hil;
    cudaGetSymbolAddress((void**)&x,    g_x);
    cudaGetSymbolAddress((void**)&qkv,  g_qkv);
    cudaGetSymbolAddress((void**)&y,    g_y);
    cudaGetSymbolAddress((void**)&p1,   g_p1);
    cudaGetSymbolAddress((void**)&p2,   g_p2);
    cudaGetSymbolAddress((void**)&s1b,  g_s1);
    cudaGetSymbolAddress((void**)&t1b,  g_t1);
    cudaGetSymbolAddress((void**)&s2b,  g_s2);
    cudaGetSymbolAddress((void**)&t2b,  g_t2);
    cudaGetSymbolAddress((void**)&bqkv, g_bqkv);
    cudaGetSymbolAddress((void**)&wh,   g_wh);
    cudaGetSymbolAddress((void**)&wl,   g_wl);
    cudaGetSymbolAddress((void**)&xih,  g_xih);
    cudaGetSymbolAddress((void**)&xil,  g_xil);
    cudaGetSymbolAddress((void**)&tih,  g_tih);
    cudaGetSymbolAddress((void**)&til,  g_til);
    cudaGetSymbolAddress((void**)&yih,  g_yih);
    cudaGetSymbolAddress((void**)&yil,  g_yil);
    cudaGetSymbolAddress((void**)&hih,  g_hih);
    cudaGetSymbolAddress((void**)&hil,  g_hil);

    cudaFuncSetAttribute(gemm_pre<0,0,0>, cudaFuncAttributeMaxDynamicSharedMemorySize, PRE_SMEM);
    cudaFuncSetAttribute(gemm_pre<0,1,0>, cudaFuncAttributeMaxDynamicSharedMemorySize, PRE_SMEM);
    cudaFuncSetAttribute(gemm_pre<1,0,1>, cudaFuncAttributeMaxDynamicSharedMemorySize, PRE_SMEM);

    float* q = qkv;
    float* k = qkv + (long)R_TOT*EDIM;
    float* v = qkv + 2L*R_TOT*EDIM;

    dim3 gE(1, R_TOT/64, 1);
    dim3 gQKV(1, R_TOT/64, 3);
    dim3 gF1(4, R_TOT/64, 1);
    dim3 gN((R_TOT*EDIM + 255)/256);
    const int gCN = R_TOT * 64 / 256;

    w_convert<<<dim3(128, 18), 256>>>(Wq, Wk, Wv, Wo, Wf1, Wf2, bq, bk, bv, bqkv, wh, wl);
    embed_kernel<<<R_TOT, EDIM>>>(s, dd, e_w, e_b, ep_w, ep_b, x);

    for (int i = 0; i < 3; i++) {
        const uint32_t* whL = wh + (long)i*98304;
        const uint32_t* wlL = wl + (long)i*98304;
        const float* bo_ = bo + i*EDIM;
        const float* b1_ = bf1 + i*FF;
        const float* b2_ = bf2 + i*EDIM;
        const float* inS = (i == 0) ? nullptr : s2b;
        const float* inT = (i == 0) ? nullptr : t2b;

        conv_norm<<<gCN, 256>>>(x, inS, inT, xih, xil);

        gemm_pre<0,0,0><<<gQKV, 256, PRE_SMEM>>>(xih, xil,
            whL, wlL, 8192, bqkv + i*384, 128,
            nullptr, nullptr, nullptr,
            qkv, (long)R_TOT*EDIM, nullptr, nullptr, nullptr, nullptr, EDIM);

        attn_kernel<<<BATCH*NHEAD, 224>>>(q, k, v, tih, til);

        gemm_pre<0,1,0><<<gE, 256, PRE_SMEM>>>(tih, til,
            whL + 24576, wlL + 24576, 0, bo_, 0,
            x, inS, inT,
            y, 0, nullptr, nullptr, p1, p2, EDIM);

        bn_final_kernel<<<EDIM, 256>>>(p1, p2, g1 + i*EDIM, be1 + i*EDIM, s1b, t1b);

        conv_norm<<<gCN, 256>>>(y, s1b, t1b, yih, yil);

        gemm_pre<1,0,1><<<gF1, 256, PRE_SMEM>>>(yih, yil,
            whL + 32768, wlL + 32768, 0, b1_, 0,
            nullptr, nullptr, nullptr,
            nullptr, 0, hih, hil, nullptr, nullptr, FF);

        gemm_tc<0,1><<<gE, 256>>>(hih, hil,
            whL + 65536, wlL + 65536, b2_,
            y, s1b, t1b,
            x, p1, p2, FF, EDIM);

        bn_final_kernel<<<EDIM, 256>>>(p1, p2, g2 + i*EDIM, be2 + i*EDIM, s2b, t2b);
    }
    bn_norm_kernel<<<gN, 256>>>(x, s2b, t2b, out);
}

// round 14
// speedup vs baseline: 1.0143x; 1.0143x over previous
#include <cuda_runtime.h>
#include <cuda_bf16.h>
#include <cstdint>
#include <math.h>

#define BATCH 512
#define NSEQ  101
#define R_TOT (BATCH*NSEQ)   // 51712
#define EDIM  128
#define NHEAD 8
#define DK    16
#define FF    512
#define NBLK_BN 808          // = R_TOT/64

typedef unsigned long long ull;

// ---------------- scratch (device globals; allocation-free) ----------------
__device__ float g_x[R_TOT*EDIM];
__device__ float g_qkv[3*R_TOT*EDIM];
__device__ float g_y[R_TOT*EDIM];
__device__ float g_p1[NBLK_BN*EDIM];
__device__ float g_p2[NBLK_BN*EDIM];
__device__ float g_s1[EDIM];
__device__ float g_t1[EDIM];
__device__ float g_s2[EDIM];
__device__ float g_t2[EDIM];
__device__ float g_bqkv[3*3*EDIM];
__device__ uint32_t g_wh[3*98304];
__device__ uint32_t g_wl[3*98304];
// activation images (swizzled bf16 hi/lo, region = 64 rows x 32 k = 1024 u32)
__device__ uint32_t g_xih[R_TOT*64];
__device__ uint32_t g_xil[R_TOT*64];
__device__ uint32_t g_tih[R_TOT*64];
__device__ uint32_t g_til[R_TOT*64];
__device__ uint32_t g_yih[R_TOT*64];
__device__ uint32_t g_yil[R_TOT*64];
__device__ uint32_t g_hih[R_TOT*256];
__device__ uint32_t g_hil[R_TOT*256];

// ======================= helpers =======================
__device__ __forceinline__ uint32_t smem_u32(const void* p) {
    uint32_t a;
    asm("{ .reg .u64 t; cvta.to.shared.u64 t, %1; cvt.u32.u64 %0, t; }" : "=r"(a) : "l"(p));
    return a;
}
__device__ __forceinline__ void ldsm_x4(uint32_t* r, uint32_t addr) {
    asm volatile("ldmatrix.sync.aligned.m8n8.x4.shared.b16 {%0,%1,%2,%3}, [%4];"
        : "=r"(r[0]), "=r"(r[1]), "=r"(r[2]), "=r"(r[3]) : "r"(addr));
}
__device__ __forceinline__ void mma16816(float* c, const uint32_t* a, const uint32_t* b) {
    asm volatile(
        "mma.sync.aligned.m16n8k16.row.col.f32.bf16.bf16.f32 "
        "{%0,%1,%2,%3}, {%4,%5,%6,%7}, {%8,%9}, {%0,%1,%2,%3};"
        : "+f"(c[0]), "+f"(c[1]), "+f"(c[2]), "+f"(c[3])
        : "r"(a[0]), "r"(a[1]), "r"(a[2]), "r"(a[3]), "r"(b[0]), "r"(b[1]));
}
__device__ __forceinline__ uint32_t pack_bf2(float x, float y) {
    __nv_bfloat162 t;
    t.x = __float2bfloat16(x); t.y = __float2bfloat16(y);
    return *reinterpret_cast<uint32_t*>(&t);
}
__device__ __forceinline__ void split_pair(float x, float y, uint32_t& hi, uint32_t& lo) {
    __nv_bfloat16 h0 = __float2bfloat16(x);
    __nv_bfloat16 h1 = __float2bfloat16(y);
    __nv_bfloat162 hp; hp.x = h0; hp.y = h1;
    hi = *(uint32_t*)&hp;
    lo = pack_bf2(x - __bfloat162float(h0), y - __bfloat162float(h1));
}
__device__ __forceinline__ void cp_async16(uint32_t saddr, const void* g) {
    asm volatile("cp.async.cg.shared.global [%0], [%1], 16;" :: "r"(saddr), "l"(g));
}
__device__ __forceinline__ void cp_commit() { asm volatile("cp.async.commit_group;"); }
__device__ __forceinline__ void cp_wait0() { asm volatile("cp.async.wait_group 0;"); }

__device__ __forceinline__ uint32_t sw_off(int row, int col8) {
    return (uint32_t)((row << 6) + ((col8 ^ ((row >> 1) & 3)) << 4));
}
__device__ __forceinline__ uint32_t img_u32(int rl, int kl) {
    return (sw_off(rl, kl >> 3) + ((kl & 7) << 1)) >> 2;
}

// ================== weight pre-conversion ==================
__global__ __launch_bounds__(256)
void w_convert(const float* __restrict__ Wq, const float* __restrict__ Wk,
               const float* __restrict__ Wv, const float* __restrict__ Wo,
               const float* __restrict__ Wf1, const float* __restrict__ Wf2,
               const float* __restrict__ bq, const float* __restrict__ bk,
               const float* __restrict__ bv, float* __restrict__ bqkv,
               uint32_t* __restrict__ oh, uint32_t* __restrict__ ol) {
    int mode = blockIdx.y;
    int idx = blockIdx.x * 256 + threadIdx.x;
    if (mode == 0 && idx < 3*3*EDIM) {
        int layer = idx / 384, w = (idx / 128) % 3, c = idx & 127;
        const float* src = (w == 0) ? bq : (w == 1) ? bk : bv;
        bqkv[idx] = src[layer * EDIM + c];
    }
    const float* src;
    int N, K, npairs, dstoff;
    if (mode < 12) {
        int layer = mode >> 2, w = mode & 3;
        const float* s;
        if (w == 0) s = Wq; else if (w == 1) s = Wk; else if (w == 2) s = Wv; else s = Wo;
        src = s + layer * 16384;
        N = 128; K = 128; npairs = 8192; dstoff = layer * 98304 + w * 8192;
    } else if (mode < 15) {
        int layer = mode - 12;
        src = Wf1 + layer * 65536;
        N = 512; K = 128; npairs = 32768; dstoff = layer * 98304 + 32768;
    } else {
        int layer = mode - 15;
        src = Wf2 + layer * 65536;
        N = 128; K = 512; npairs = 32768; dstoff = layer * 98304 + 65536;
    }
    if (idx >= npairs) return;
    int n = idx & (N - 1);
    int k2g = idx / N;
    float x0 = src[(long)(2 * k2g) * N + n];
    float x1 = src[(long)(2 * k2g + 1) * N + n];
    int c = k2g >> 4, kl = (k2g & 15) * 2;
    int nb = n >> 7, nl = n & 127;
    uint32_t u = (uint32_t)dstoff + (uint32_t)(nb * (K >> 5) + c) * 2048
               + ((sw_off(nl, kl >> 3) + ((kl & 7) << 1)) >> 2);
    uint32_t hi, lo;
    split_pair(x0, x1, hi, lo);
    oh[u] = hi; ol[u] = lo;
}

// ================== activation -> normed bf16 hi/lo image ==================
__global__ __launch_bounds__(256)
void conv_norm(const float* __restrict__ X,
               const float* __restrict__ S, const float* __restrict__ T,
               uint32_t* __restrict__ oh, uint32_t* __restrict__ ol) {
    int idx = blockIdx.x * 256 + threadIdx.x;
    int row = idx >> 6, p2 = idx & 63;
    float2 a = *(const float2*)(X + (long)row * 128 + 2 * p2);
    if (S) {
        int c0 = 2 * p2;
        a.x = a.x * __ldg(S + c0)     + __ldg(T + c0);
        a.y = a.y * __ldg(S + c0 + 1) + __ldg(T + c0 + 1);
    }
    int rl = row & 63, c = p2 >> 4, kl = (2 * p2) & 31;
    uint32_t u = ((uint32_t)(row >> 6) * 4 + c) * 1024 + img_u32(rl, kl);
    uint32_t hi, lo;
    split_pair(a.x, a.y, hi, lo);
    oh[u] = hi; ol[u] = lo;
}

// ================== 128x128 chunked GEMM (8 warps, 32x64 warp tiles) ==================
// dynamic smem 64KB: buf*32768 { AH 8K | AL 8K | BH 8K | BL 8K }
#define BOFF_A(buf)  ((buf)*32768)
#define BOFF_B(buf)  ((buf)*32768 + 16384)
#define BIG_SMEM 65536
template<int RELU, int WIMG>
__global__ __launch_bounds__(256, 2)
void gemm_big(const uint32_t* __restrict__ Ah, const uint32_t* __restrict__ Al,
              const uint32_t* __restrict__ Wh_, const uint32_t* __restrict__ Wl_, int wstride,
              const float* __restrict__ bias_, int bstride,
              float* __restrict__ C_, long cstride,
              uint32_t* __restrict__ Hh, uint32_t* __restrict__ Hl,
              int K, int Nout)
{
    extern __shared__ __align__(128) char smd[];
    const uint32_t usm = smem_u32(smd);

    const uint32_t* Wh = Wh_ + (long)blockIdx.z * wstride;
    const uint32_t* Wl = Wl_ + (long)blockIdx.z * wstride;
    const float* bias = bias_ + blockIdx.z * bstride;
    float* C = C_ + (long)blockIdx.z * cstride;

    const int tid  = threadIdx.x;
    const int lane = tid & 31;
    const int warp = tid >> 5;
    const int wm = (warp & 3) * 32;
    const int wn = (warp >> 2) * 64;
    const int m0 = blockIdx.y * 128;
    const int n0 = blockIdx.x * 128;
    const int nchunks = K >> 5;
    const long bregbase = (long)blockIdx.x * nchunks;

    float acc[2][8][4];
#pragma unroll
    for (int i = 0; i < 2; i++)
#pragma unroll
        for (int j = 0; j < 8; j++)
#pragma unroll
            for (int q = 0; q < 4; q++) acc[i][j][q] = 0.f;

    // prologue chunk 0
    {
#pragma unroll
        for (int half = 0; half < 2; half++) {
            long areg = ((long)(blockIdx.y * 2 + half) * nchunks) * 1024;
            cp_async16(usm + BOFF_A(0) + half * 4096 + tid * 16, Ah + areg + tid * 4);
            cp_async16(usm + BOFF_A(0) + 8192 + half * 4096 + tid * 16, Al + areg + tid * 4);
        }
        const uint32_t* bh = Wh + bregbase * 2048 + tid * 8;
        const uint32_t* bl = Wl + bregbase * 2048 + tid * 8;
        cp_async16(usm + BOFF_B(0) + tid * 32,      bh);
        cp_async16(usm + BOFF_B(0) + tid * 32 + 16, bh + 4);
        cp_async16(usm + BOFF_B(0) + 8192 + tid * 32,      bl);
        cp_async16(usm + BOFF_B(0) + 8192 + tid * 32 + 16, bl + 4);
        cp_commit();
        cp_wait0();
        __syncthreads();
    }

    for (int c = 0; c < nchunks; c++) {
        const int cur = c & 1, nxt = cur ^ 1;
        const bool hn = (c + 1) < nchunks;
        if (hn) {
#pragma unroll
            for (int half = 0; half < 2; half++) {
                long areg = ((long)(blockIdx.y * 2 + half) * nchunks + c + 1) * 1024;
                cp_async16(usm + BOFF_A(nxt) + half * 4096 + tid * 16, Ah + areg + tid * 4);
                cp_async16(usm + BOFF_A(nxt) + 8192 + half * 4096 + tid * 16, Al + areg + tid * 4);
            }
            const uint32_t* bh = Wh + (bregbase + c + 1) * 2048 + tid * 8;
            const uint32_t* bl = Wl + (bregbase + c + 1) * 2048 + tid * 8;
            cp_async16(usm + BOFF_B(nxt) + tid * 32,      bh);
            cp_async16(usm + BOFF_B(nxt) + tid * 32 + 16, bh + 4);
            cp_async16(usm + BOFF_B(nxt) + 8192 + tid * 32,      bl);
            cp_async16(usm + BOFF_B(nxt) + 8192 + tid * 32 + 16, bl + 4);
            cp_commit();
        }
#pragma unroll
        for (int kk = 0; kk < 32; kk += 16) {
            uint32_t ah[2][4], al[2][4];
#pragma unroll
            for (int mi = 0; mi < 2; mi++) {
                int arow = wm + mi * 16 + (lane & 15);
                uint32_t off = usm + BOFF_A(cur) + ((arow >> 6) << 12)
                             + sw_off(arow & 63, (kk >> 3) + (lane >> 4));
                ldsm_x4(ah[mi], off);
                ldsm_x4(al[mi], off + 8192);
            }
#pragma unroll
            for (int np = 0; np < 4; np++) {
                uint32_t bh[4], bl[4];
                int nrow = wn + np * 16 + (lane & 7) + ((lane >> 4) << 3);
                uint32_t boff = usm + BOFF_B(cur) + sw_off(nrow, (kk >> 3) + ((lane >> 3) & 1));
                ldsm_x4(bh, boff);
                ldsm_x4(bl, boff + 8192);
#pragma unroll
                for (int t = 0; t < 2; t++) {
#pragma unroll
                    for (int mi = 0; mi < 2; mi++) {
                        float* cc = acc[mi][np * 2 + t];
                        mma16816(cc, ah[mi], bh + t * 2);
                        mma16816(cc, ah[mi], bl + t * 2);
                        mma16816(cc, al[mi], bh + t * 2);
                    }
                }
            }
        }
        if (hn) {
            cp_wait0();
            __syncthreads();
        }
    }

    const int group = lane >> 2, tig = lane & 3;

    if (WIMG) {
        __syncthreads();
        uint32_t* smH = (uint32_t*)smd;           // 8192 u32
        uint32_t* smL = smH + 8192;               // 8192 u32
#pragma unroll
        for (int mi = 0; mi < 2; mi++) {
#pragma unroll
            for (int np = 0; np < 4; np++) {
#pragma unroll
                for (int t = 0; t < 2; t++) {
                    float* cc = acc[mi][np * 2 + t];
                    int rl = wm + mi * 16 + group;
                    int cl = wn + np * 16 + t * 8 + tig * 2;
                    float b0 = bias[n0 + cl], b1 = bias[n0 + cl + 1];
                    float v0 = cc[0] + b0, v1 = cc[1] + b1;
                    float v2 = cc[2] + b0, v3 = cc[3] + b1;
                    if (RELU) {
                        v0 = fmaxf(v0, 0.f); v1 = fmaxf(v1, 0.f);
                        v2 = fmaxf(v2, 0.f); v3 = fmaxf(v3, 0.f);
                    }
                    int ch = cl >> 5, kl = cl & 31;
                    uint32_t o1 = ((rl >> 6) * 4 + ch) * 1024 + img_u32(rl & 63, kl);
                    int rl2 = rl + 8;
                    uint32_t o2 = ((rl2 >> 6) * 4 + ch) * 1024 + img_u32(rl2 & 63, kl);
                    uint32_t hi, lo;
                    split_pair(v0, v1, hi, lo);
                    smH[o1] = hi; smL[o1] = lo;
                    split_pair(v2, v3, hi, lo);
                    smH[o2] = hi; smL[o2] = lo;
                }
            }
        }
        __syncthreads();
#pragma unroll
        for (int half = 0; half < 2; half++) {
            long gbase = ((long)(blockIdx.y * 2 + half) * (Nout >> 5) + (n0 >> 5)) * 1024;
            uint4* gh = (uint4*)(Hh + gbase);
            uint4* gl = (uint4*)(Hl + gbase);
            const uint4* sh4 = (const uint4*)(smH + half * 4096);
            const uint4* sl4 = (const uint4*)(smL + half * 4096);
#pragma unroll
            for (int i = 0; i < 4; i++) {
                gh[tid + i * 256] = sh4[tid + i * 256];
                gl[tid + i * 256] = sl4[tid + i * 256];
            }
        }
        return;
    }

    // plain epilogue: bias only (QKV)
#pragma unroll
    for (int mi = 0; mi < 2; mi++) {
#pragma unroll
        for (int np = 0; np < 4; np++) {
#pragma unroll
            for (int t = 0; t < 2; t++) {
                float* cc = acc[mi][np * 2 + t];
                int row = m0 + wm + mi * 16 + group;
                int col = n0 + wn + np * 16 + t * 8 + tig * 2;
                float b0 = bias[col], b1 = bias[col + 1];
                float2 p0 = {cc[0] + b0, cc[1] + b1};
                float2 p1 = {cc[2] + b0, cc[3] + b1};
                *(float2*)(C + (long)row * Nout + col) = p0;
                *(float2*)(C + (long)(row + 8) * Nout + col) = p1;
            }
        }
    }
}

// ================== 64x128 chunked GEMM with STATS (Wo, FF2) ==================
#define OFF_A(buf,hl) (((((buf)<<1)+(hl))<<12))
#define OFF_B(buf,hl) (16384 + (((((buf)<<1)+(hl))<<13)))
template<int RELU, int STATS>
__global__ __launch_bounds__(256, 3)
void gemm_tc(const uint32_t* __restrict__ Ah, const uint32_t* __restrict__ Al,
             const uint32_t* __restrict__ Wh, const uint32_t* __restrict__ Wl,
             const float* __restrict__ bias,
             const float* __restrict__ res,
             const float* __restrict__ Rs_, const float* __restrict__ Rt_,
             float* __restrict__ C,
             float* __restrict__ P1, float* __restrict__ P2,
             int K, int Nout)
{
    __shared__ __align__(128) char sm[49152];
    const uint32_t usm = smem_u32(sm);

    const int tid  = threadIdx.x;
    const int lane = tid & 31;
    const int warp = tid >> 5;
    const int wm = (warp & 1) * 32;
    const int wn = (warp >> 1) * 32;
    const int m0 = blockIdx.y * 64;
    const int n0 = blockIdx.x * 128;
    const int nchunks = K >> 5;
    const long bregbase = (long)blockIdx.x * nchunks;
    const long aregbase = (long)blockIdx.y * nchunks;

    float acc[2][4][4];
#pragma unroll
    for (int i = 0; i < 2; i++)
#pragma unroll
        for (int j = 0; j < 4; j++)
#pragma unroll
            for (int q = 0; q < 4; q++) acc[i][j][q] = 0.f;

    {
        const uint32_t* bh = Wh + bregbase * 2048 + tid * 8;
        const uint32_t* bl = Wl + bregbase * 2048 + tid * 8;
        cp_async16(usm + OFF_B(0,0) + tid * 32,      bh);
        cp_async16(usm + OFF_B(0,0) + tid * 32 + 16, bh + 4);
        cp_async16(usm + OFF_B(0,1) + tid * 32,      bl);
        cp_async16(usm + OFF_B(0,1) + tid * 32 + 16, bl + 4);
        cp_async16(usm + OFF_A(0,0) + tid * 16, Ah + aregbase * 1024 + tid * 4);
        cp_async16(usm + OFF_A(0,1) + tid * 16, Al + aregbase * 1024 + tid * 4);
        cp_commit();
        cp_wait0();
        __syncthreads();
    }

    for (int c = 0; c < nchunks; c++) {
        const int cur = c & 1, nxt = cur ^ 1;
        const bool hn = (c + 1) < nchunks;
        if (hn) {
            const uint32_t* bh = Wh + (bregbase + c + 1) * 2048 + tid * 8;
            const uint32_t* bl = Wl + (bregbase + c + 1) * 2048 + tid * 8;
            cp_async16(usm + OFF_B(nxt,0) + tid * 32,      bh);
            cp_async16(usm + OFF_B(nxt,0) + tid * 32 + 16, bh + 4);
            cp_async16(usm + OFF_B(nxt,1) + tid * 32,      bl);
            cp_async16(usm + OFF_B(nxt,1) + tid * 32 + 16, bl + 4);
            cp_async16(usm + OFF_A(nxt,0) + tid * 16, Ah + (aregbase + c + 1) * 1024 + tid * 4);
            cp_async16(usm + OFF_A(nxt,1) + tid * 16, Al + (aregbase + c + 1) * 1024 + tid * 4);
            cp_commit();
        }
#pragma unroll
        for (int kk = 0; kk < 32; kk += 16) {
            uint32_t ah[2][4], al[2][4];
#pragma unroll
            for (int mi = 0; mi < 2; mi++) {
                int arow = wm + mi * 16 + (lane & 15);
                uint32_t off = OFF_A(cur,0) + sw_off(arow, (kk >> 3) + (lane >> 4));
                ldsm_x4(ah[mi], usm + off);
                ldsm_x4(al[mi], usm + off + 4096);
            }
#pragma unroll
            for (int np = 0; np < 2; np++) {
                uint32_t bh[4], bl[4];
                int nrow = wn + np * 16 + (lane & 7) + ((lane >> 4) << 3);
                uint32_t boff = OFF_B(cur,0) + sw_off(nrow, (kk >> 3) + ((lane >> 3) & 1));
                ldsm_x4(bh, usm + boff);
                ldsm_x4(bl, usm + boff + 8192);
#pragma unroll
                for (int t = 0; t < 2; t++) {
#pragma unroll
                    for (int mi = 0; mi < 2; mi++) {
                        float* cc = acc[mi][np * 2 + t];
                        mma16816(cc, ah[mi], bh + t * 2);
                        mma16816(cc, ah[mi], bl + t * 2);
                        mma16816(cc, al[mi], bh + t * 2);
                    }
                }
            }
        }
        if (hn) {
            cp_wait0();
            __syncthreads();
        }
    }

    const int group = lane >> 2, tig = lane & 3;
    float s1L[8], s2L[8];
    if (STATS) {
#pragma unroll
        for (int i = 0; i < 8; i++) { s1L[i] = 0.f; s2L[i] = 0.f; }
    }
#pragma unroll
    for (int mi = 0; mi < 2; mi++) {
#pragma unroll
        for (int np = 0; np < 2; np++) {
#pragma unroll
            for (int t = 0; t < 2; t++) {
                float* cc = acc[mi][np * 2 + t];
                int row = m0 + wm + mi * 16 + group;
                int col = n0 + wn + np * 16 + t * 8 + tig * 2;
                float b0 = bias[col], b1 = bias[col + 1];
                float v0 = cc[0] + b0, v1 = cc[1] + b1;
                float v2 = cc[2] + b0, v3 = cc[3] + b1;
                if (res) {
                    float r0 = res[(long)row * 128 + col];
                    float r1 = res[(long)row * 128 + col + 1];
                    float r2 = res[(long)(row + 8) * 128 + col];
                    float r3 = res[(long)(row + 8) * 128 + col + 1];
                    if (Rs_) {
                        float s0 = __ldg(Rs_ + col), s1 = __ldg(Rs_ + col + 1);
                        float t0 = __ldg(Rt_ + col), t1 = __ldg(Rt_ + col + 1);
                        r0 = r0 * s0 + t0; r1 = r1 * s1 + t1;
                        r2 = r2 * s0 + t0; r3 = r3 * s1 + t1;
                    }
                    v0 += r0; v1 += r1; v2 += r2; v3 += r3;
                }
                if (RELU) {
                    v0 = fmaxf(v0, 0.f); v1 = fmaxf(v1, 0.f);
                    v2 = fmaxf(v2, 0.f); v3 = fmaxf(v3, 0.f);
                }
                if (STATS) {
                    int kk = np * 4 + t * 2;
                    s1L[kk]     += v0 + v2;
                    s1L[kk + 1] += v1 + v3;
                    s2L[kk]     += v0 * v0 + v2 * v2;
                    s2L[kk + 1] += v1 * v1 + v3 * v3;
                }
                float2 p0 = {v0, v1}, p1 = {v2, v3};
                *(float2*)(C + (long)row * Nout + col) = p0;
                *(float2*)(C + (long)(row + 8) * Nout + col) = p1;
            }
        }
    }
    if (STATS) {
#pragma unroll
        for (int m = 4; m <= 16; m <<= 1) {
#pragma unroll
            for (int kk = 0; kk < 8; kk++) {
                s1L[kk] += __shfl_xor_sync(0xFFFFFFFF, s1L[kk], m);
                s2L[kk] += __shfl_xor_sync(0xFFFFFFFF, s2L[kk], m);
            }
        }
        __syncthreads();
        float* sb = (float*)sm;
        if (lane < 4) {
#pragma unroll
            for (int kk = 0; kk < 8; kk++) {
                int col = wn + ((kk >> 2) * 16) + (((kk >> 1) & 1) * 8) + lane * 2 + (kk & 1);
                int idx2 = ((warp & 1) << 7) + col;
                sb[idx2] = s1L[kk];
                sb[256 + idx2] = s2L[kk];
            }
        }
        __syncthreads();
        if (tid < 128) {
            P1[blockIdx.y * 128 + tid] = sb[tid] + sb[128 + tid];
            P2[blockIdx.y * 128 + tid] = sb[256 + tid] + sb[384 + tid];
        }
    }
}

// ---------------- embedding ----------------
__global__ void embed_kernel(const float* __restrict__ s, const int* __restrict__ d,
                             const float* __restrict__ e_w, const float* __restrict__ e_b,
                             const float* __restrict__ ep_w, const float* __restrict__ ep_b,
                             float* __restrict__ x) {
    int r = blockIdx.x;
    int e = threadIdx.x;
    int n = r % NSEQ;
    float s0 = s[r*2+0], s1 = s[r*2+1];
    float out;
    if (n == 0) {
        out = ep_b[e] + s0*ep_w[e] + s1*ep_w[EDIM+e];
    } else {
        float dd = (float)d[r];
        out = e_b[e] + s0*e_w[e] + s1*e_w[EDIM+e] + dd*e_w[2*EDIM+e];
    }
    x[r*EDIM+e] = out;
}

// ---------------- attention: tensor-core (HMMA) flash-style, per (b,h) block ----------------
#define QK_STR 48
#define VT_STR 240
#define AQH 0
#define AQL 5376
#define AKH 10752
#define AKL 16128
#define AVH 21504
#define AVL 25344
#define ATTN_SM 29184
__global__ __launch_bounds__(224, 2)
void attn_kernel(const float* __restrict__ q, const float* __restrict__ k,
                 const float* __restrict__ v,
                 uint32_t* __restrict__ th, uint32_t* __restrict__ tl) {
    __shared__ __align__(128) char sm[ATTN_SM];
    const uint32_t usm = smem_u32(sm);
    int bh = blockIdx.x;
    int b = bh >> 3, h = bh & 7;
    int tid = threadIdx.x, lane = tid & 31, warp = tid >> 5;
    long base = (long)b * NSEQ * EDIM + h * DK;

    for (int i = tid; i < ATTN_SM/16; i += 224)
        ((uint4*)sm)[i] = make_uint4(0,0,0,0);
    __syncthreads();

    for (int idx = tid; idx < NSEQ*8; idx += 224) {
        int r = idx >> 3, d2 = idx & 7;
        float2 qv = *(const float2*)(q + base + (long)r*EDIM + 2*d2);
        float2 kv = *(const float2*)(k + base + (long)r*EDIM + 2*d2);
        float2 vv = *(const float2*)(v + base + (long)r*EDIM + 2*d2);
        uint32_t hi, lo;
        split_pair(qv.x, qv.y, hi, lo);
        *(uint32_t*)(sm + AQH + r*QK_STR + 4*d2) = hi;
        *(uint32_t*)(sm + AQL + r*QK_STR + 4*d2) = lo;
        split_pair(kv.x, kv.y, hi, lo);
        *(uint32_t*)(sm + AKH + r*QK_STR + 4*d2) = hi;
        *(uint32_t*)(sm + AKL + r*QK_STR + 4*d2) = lo;
        __nv_bfloat16 h0 = __float2bfloat16(vv.x);
        __nv_bfloat16 h1 = __float2bfloat16(vv.y);
        *(__nv_bfloat16*)(sm + AVH + (2*d2)*VT_STR + 2*r) = h0;
        *(__nv_bfloat16*)(sm + AVH + (2*d2+1)*VT_STR + 2*r) = h1;
        *(__nv_bfloat16*)(sm + AVL + (2*d2)*VT_STR + 2*r) =
            __float2bfloat16(vv.x - __bfloat162float(h0));
        *(__nv_bfloat16*)(sm + AVL + (2*d2+1)*VT_STR + 2*r) =
            __float2bfloat16(vv.y - __bfloat162float(h1));
    }
    __syncthreads();

    const int mt = warp;
    const int g = lane >> 2, tig = lane & 3;

    uint32_t qh[4], ql[4];
    {
        uint32_t addr = usm + AQH + (mt*16 + (lane & 15)) * QK_STR + ((lane >> 4) << 4);
        ldsm_x4(qh, addr);
        ldsm_x4(ql, addr + (AQL - AQH));
    }

    float sc[14][4];
#pragma unroll
    for (int i = 0; i < 14; i++)
#pragma unroll
        for (int j = 0; j < 4; j++) sc[i][j] = 0.f;
#pragma unroll
    for (int kp = 0; kp < 7; kp++) {
        uint32_t kbh[4], kbl[4];
        uint32_t addr = usm + AKH + (kp*16 + (lane & 7) + ((lane >> 4) << 3)) * QK_STR
                      + (((lane >> 3) & 1) << 4);
        ldsm_x4(kbh, addr);
        ldsm_x4(kbl, addr + (AKL - AKH));
#pragma unroll
        for (int t = 0; t < 2; t++) {
            float* cc = sc[2*kp + t];
            mma16816(cc, qh, kbh + t*2);
            mma16816(cc, qh, kbl + t*2);
            mma16816(cc, ql, kbh + t*2);
        }
    }

    float l0 = 0.f, l1 = 0.f;
#pragma unroll
    for (int nt = 0; nt < 14; nt++) {
        int colb = nt*8 + tig*2;
        float e0 = (colb     < NSEQ) ? __expf(sc[nt][0] * 0.25f) : 0.f;
        float e1 = (colb + 1 < NSEQ) ? __expf(sc[nt][1] * 0.25f) : 0.f;
        float e2 = (colb     < NSEQ) ? __expf(sc[nt][2] * 0.25f) : 0.f;
        float e3 = (colb + 1 < NSEQ) ? __expf(sc[nt][3] * 0.25f) : 0.f;
        sc[nt][0] = e0; sc[nt][1] = e1; sc[nt][2] = e2; sc[nt][3] = e3;
        l0 += e0 + e1; l1 += e2 + e3;
    }
    l0 += __shfl_xor_sync(0xFFFFFFFF, l0, 1);
    l0 += __shfl_xor_sync(0xFFFFFFFF, l0, 2);
    l1 += __shfl_xor_sync(0xFFFFFFFF, l1, 1);
    l1 += __shfl_xor_sync(0xFFFFFFFF, l1, 2);
    float inv0 = 1.f / l0, inv1 = 1.f / l1;

    float oa[2][4];
#pragma unroll
    for (int i = 0; i < 2; i++)
#pragma unroll
        for (int j = 0; j < 4; j++) oa[i][j] = 0.f;
#pragma unroll
    for (int kc = 0; kc < 7; kc++) {
        uint32_t ah4[4], al4[4];
        float* s0 = sc[2*kc]; float* s1 = sc[2*kc + 1];
        split_pair(s0[0], s0[1], ah4[0], al4[0]);
        split_pair(s0[2], s0[3], ah4[1], al4[1]);
        split_pair(s1[0], s1[1], ah4[2], al4[2]);
        split_pair(s1[2], s1[3], ah4[3], al4[3]);
        uint32_t vbh[4], vbl[4];
        uint32_t addr = usm + AVH + ((lane & 7) + ((lane >> 4) << 3)) * VT_STR
                      + (kc << 5) + (((lane >> 3) & 1) << 4);
        ldsm_x4(vbh, addr);
        ldsm_x4(vbl, addr + (AVL - AVH));
#pragma unroll
        for (int d = 0; d < 2; d++) {
            float* cc = oa[d];
            mma16816(cc, ah4, vbh + d*2);
            mma16816(cc, ah4, vbl + d*2);
            mma16816(cc, al4, vbh + d*2);
        }
    }

#pragma unroll
    for (int d = 0; d < 2; d++) {
        int qr = mt*16 + g;
        if (qr < NSEQ) {
            int row = b * NSEQ + qr;
            uint32_t regb = ((uint32_t)(row >> 6) * 4 + (h >> 1)) * 1024;
            int kl = (h & 1) * 16 + d*8 + 2*tig;
            uint32_t u = regb + img_u32(row & 63, kl);
            uint32_t hi, lo;
            split_pair(oa[d][0]*inv0, oa[d][1]*inv0, hi, lo);
            th[u] = hi; tl[u] = lo;
        }
        if (qr + 8 < NSEQ) {
            int row = b * NSEQ + qr + 8;
            uint32_t regb = ((uint32_t)(row >> 6) * 4 + (h >> 1)) * 1024;
            int kl = (h & 1) * 16 + d*8 + 2*tig;
            uint32_t u = regb + img_u32(row & 63, kl);
            uint32_t hi, lo;
            split_pair(oa[d][2]*inv1, oa[d][3]*inv1, hi, lo);
            th[u] = hi; tl[u] = lo;
        }
    }
}

// ---------------- batchnorm finalize (one block per channel) ----------------
__global__ __launch_bounds__(256)
void bn_final_kernel(const float* __restrict__ p1, const float* __restrict__ p2,
                     const float* __restrict__ g, const float* __restrict__ be,
                     float* __restrict__ s, float* __restrict__ t) {
    int c = blockIdx.x;
    int tid = threadIdx.x, lane = tid & 31, warp = tid >> 5;
    float s1 = 0.f, s2 = 0.f;
    for (int b = tid; b < NBLK_BN; b += 256) {
        s1 += p1[(long)b*EDIM + c];
        s2 += p2[(long)b*EDIM + c];
    }
#pragma unroll
    for (int m = 16; m >= 1; m >>= 1) {
        s1 += __shfl_xor_sync(0xFFFFFFFF, s1, m);
        s2 += __shfl_xor_sync(0xFFFFFFFF, s2, m);
    }
    __shared__ float sh[2][8];
    if (lane == 0) { sh[0][warp] = s1; sh[1][warp] = s2; }
    __syncthreads();
    if (tid == 0) {
        float a1 = 0.f, a2 = 0.f;
#pragma unroll
        for (int w = 0; w < 8; w++) { a1 += sh[0][w]; a2 += sh[1][w]; }
        float mu = a1 / (float)R_TOT;
        float var = a2 / (float)R_TOT - mu*mu;
        float istd = rsqrtf(var + 1e-5f);
        float scv = istd * g[c];
        s[c] = scv;
        t[c] = be[c] - mu * scv;
    }
}

__global__ __launch_bounds__(256)
void bn_norm_kernel(const float* __restrict__ y,
                    const float* __restrict__ s, const float* __restrict__ t,
                    float* __restrict__ outp) {
    long idx = (long)blockIdx.x * blockDim.x + threadIdx.x;
    if (idx < (long)R_TOT*EDIM) {
        int c = (int)(idx & 127);
        outp[idx] = y[idx] * s[c] + t[c];
    }
}

// ---------------- orchestration ----------------
extern "C" void kernel_launch(void* const* d_in, const int* in_sizes, int n_in,
                              void* d_out, int out_size) {
    const float* s    = (const float*)d_in[0];
    const int*   dd   = (const int*)  d_in[1];
    const float* e_w  = (const float*)d_in[2];
    const float* e_b  = (const float*)d_in[3];
    const float* ep_w = (const float*)d_in[4];
    const float* ep_b = (const float*)d_in[5];
    const float* Wq   = (const float*)d_in[6];
    const float* bq   = (const float*)d_in[7];
    const float* Wk   = (const float*)d_in[8];
    const float* bk   = (const float*)d_in[9];
    const float* Wv   = (const float*)d_in[10];
    const float* bv   = (const float*)d_in[11];
    const float* Wo   = (const float*)d_in[12];
    const float* bo   = (const float*)d_in[13];
    const float* Wf1  = (const float*)d_in[14];
    const float* bf1  = (const float*)d_in[15];
    const float* Wf2  = (const float*)d_in[16];
    const float* bf2  = (const float*)d_in[17];
    const float* g1   = (const float*)d_in[18];
    const float* be1  = (const float*)d_in[19];
    const float* g2   = (const float*)d_in[20];
    const float* be2  = (const float*)d_in[21];
    float* out = (float*)d_out;

    float *x, *qkv, *y, *p1, *p2, *s1b, *t1b, *s2b, *t2b, *bqkv;
    uint32_t *wh, *wl, *xih, *xil, *tih, *til, *yih, *yil, *hih, *hil;
    cudaGetSymbolAddress((void**)&x,    g_x);
    cudaGetSymbolAddress((void**)&qkv,  g_qkv);
    cudaGetSymbolAddress((void**)&y,    g_y);
    cudaGetSymbolAddress((void**)&p1,   g_p1);
    cudaGetSymbolAddress((void**)&p2,   g_p2);
    cudaGetSymbolAddress((void**)&s1b,  g_s1);
    cudaGetSymbolAddress((void**)&t1b,  g_t1);
    cudaGetSymbolAddress((void**)&s2b,  g_s2);
    cudaGetSymbolAddress((void**)&t2b,  g_t2);
    cudaGetSymbolAddress((void**)&bqkv, g_bqkv);
    cudaGetSymbolAddress((void**)&wh,   g_wh);
    cudaGetSymbolAddress((void**)&wl,   g_wl);
    cudaGetSymbolAddress((void**)&xih,  g_xih);
    cudaGetSymbolAddress((void**)&xil,  g_xil);
    cudaGetSymbolAddress((void**)&tih,  g_tih);
    cudaGetSymbolAddress((void**)&til,  g_til);
    cudaGetSymbolAddress((void**)&yih,  g_yih);
    cudaGetSymbolAddress((void**)&yil,  g_yil);
    cudaGetSymbolAddress((void**)&hih,  g_hih);
    cudaGetSymbolAddress((void**)&hil,  g_hil);

    cudaFuncSetAttribute(gemm_big<0,0>, cudaFuncAttributeMaxDynamicSharedMemorySize, BIG_SMEM);
    cudaFuncSetAttribute(gemm_big<1,1>, cudaFuncAttributeMaxDynamicSharedMemorySize, BIG_SMEM);

    float* q = qkv;
    float* k = qkv + (long)R_TOT*EDIM;
    float* v = qkv + 2L*R_TOT*EDIM;

    dim3 gE(1, R_TOT/64, 1);
    dim3 gQKV(1, R_TOT/128, 3);
    dim3 gF1(4, R_TOT/128, 1);
    dim3 gN((R_TOT*EDIM + 255)/256);
    const int gCN = R_TOT * 64 / 256;

    w_convert<<<dim3(128, 18), 256>>>(Wq, Wk, Wv, Wo, Wf1, Wf2, bq, bk, bv, bqkv, wh, wl);
    embed_kernel<<<R_TOT, EDIM>>>(s, dd, e_w, e_b, ep_w, ep_b, x);

    for (int i = 0; i < 3; i++) {
        const uint32_t* whL = wh + (long)i*98304;
        const uint32_t* wlL = wl + (long)i*98304;
        const float* bo_ = bo + i*EDIM;
        const float* b1_ = bf1 + i*FF;
        const float* b2_ = bf2 + i*EDIM;
        const float* inS = (i == 0) ? nullptr : s2b;
        const float* inT = (i == 0) ? nullptr : t2b;

        conv_norm<<<gCN, 256>>>(x, inS, inT, xih, xil);

        // QKV: 128x128 tile, fused over z
        gemm_big<0,0><<<gQKV, 256, BIG_SMEM>>>(xih, xil,
            whL, wlL, 8192, bqkv + i*384, 128,
            qkv, (long)R_TOT*EDIM, nullptr, nullptr, EDIM, EDIM);

        attn_kernel<<<BATCH*NHEAD, 224>>>(q, k, v, tih, til);

        gemm_tc<0,1><<<gE, 256>>>(tih, til,
            whL + 24576, wlL + 24576, bo_,
            x, inS, inT,
            y, p1, p2, EDIM, EDIM);

        bn_final_kernel<<<EDIM, 256>>>(p1, p2, g1 + i*EDIM, be1 + i*EDIM, s1b, t1b);

        conv_norm<<<gCN, 256>>>(y, s1b, t1b, yih, yil);

        // FF1: 128x128 tile, writes h image
        gemm_big<1,1><<<gF1, 256, BIG_SMEM>>>(yih, yil,
            whL + 32768, wlL + 32768, 0, b1_, 0,
            nullptr, 0, hih, hil, EDIM, FF);

        gemm_tc<0,1><<<gE, 256>>>(hih, hil,
            whL + 65536, wlL + 65536, b2_,
            y, s1b, t1b,
            x, p1, p2, FF, EDIM);

        bn_final_kernel<<<EDIM, 256>>>(p1, p2, g2 + i*EDIM, be2 + i*EDIM, s2b, t2b);
    }
    bn_norm_kernel<<<gN, 256>>>(x, s2b, t2b, out);
}